// round 5
// baseline (speedup 1.0000x reference)
#include <cuda_runtime.h>
#include <cuda_bf16.h>
#include <cstdint>

#define B 4
#define L 1024
#define D 768
#define H 12
#define NE 42
#define M 8
#define NE2 (NE*NE)   /* 1764 */
#define LC 16

// Scratch (pre-split bf16 operands)
__device__ __align__(16) float g_ent_att[B*H*NE*L];                  // [B][H][NE][L]
__device__ __align__(16) __nv_bfloat16 g_htH[(size_t)B*NE2*L];       // hi(ht)
__device__ __align__(16) __nv_bfloat16 g_htL[(size_t)B*NE2*L];       // lo(ht)
__device__ __align__(16) __nv_bfloat16 g_seqH[(size_t)B*L*D];        // hi(seq)
__device__ __align__(16) __nv_bfloat16 g_seqL[(size_t)B*L*D];        // lo(seq)
__device__ float g_rowsum[B*NE2];

__device__ __forceinline__ uint32_t smem_u32(const void* p) {
    uint32_t a;
    asm("{ .reg .u64 t; cvta.to.shared.u64 t, %1; cvt.u32.u64 %0, t; }" : "=r"(a) : "l"(p));
    return a;
}

// ---------------------------------------------------------------------------
// K1: ent_att[b,h,s,l] — one float4 of l per thread, 8-way gather
// ---------------------------------------------------------------------------
__global__ void k_ent_att(const float* __restrict__ att,
                          const int* __restrict__ midx,
                          const int* __restrict__ mmask) {
    int id = blockIdx.x;
    int s  = id % NE;
    int bh = id / NE;
    int b  = bh / H;

    int rows[M];
    int nv = 0;
#pragma unroll
    for (int m = 0; m < M; m++) {
        int base = (b*NE + s)*M + m;
        int idx = midx[base] + 1;
        bool v = (mmask[base] > 0) && (idx < L);
        rows[m] = v ? idx : -1;
        nv += v ? 1 : 0;
    }
    float inv = 1.0f / (float)(nv < 1 ? 1 : nv);

    const float* abh = att + (size_t)bh * L * L;
    float* outp = g_ent_att + (size_t)id * L;

    int l = threadIdx.x * 4;          // 256 threads x 4 = 1024
    float4 acc = make_float4(0.f, 0.f, 0.f, 0.f);
#pragma unroll
    for (int m = 0; m < M; m++) {
        if (rows[m] >= 0) {
            float4 v = *(const float4*)&abh[(size_t)rows[m]*L + l];
            acc.x += v.x; acc.y += v.y; acc.z += v.z; acc.w += v.w;
        }
    }
    acc.x *= inv; acc.y *= inv; acc.z *= inv; acc.w *= inv;
    *(float4*)&outp[l] = acc;
}

// ---------------------------------------------------------------------------
// K2: ht (bf16 hi/lo direct write) + fused rowsum
// ---------------------------------------------------------------------------
__global__ void k_ht() {
    __shared__ float Es[H*NE*(LC+1)];
    int nchunk = L / LC;
    int b  = blockIdx.x / nchunk;
    int l0 = (blockIdx.x % nchunk) * LC;

    for (int i = threadIdx.x; i < H*NE*LC; i += blockDim.x) {
        int lc = i % LC;
        int hs = i / LC;
        Es[hs*(LC+1) + lc] = g_ent_att[(size_t)(b*H*NE + hs)*L + l0 + lc];
    }
    __syncthreads();

    int tid = threadIdx.x;
    if (tid >= 252) return;
    int s  = tid / 6;
    int t0 = (tid % 6) * 7;
    const float invH = 1.0f / (float)H;

    float rs[7];
#pragma unroll
    for (int tt = 0; tt < 7; tt++) rs[tt] = 0.0f;

    for (int l = 0; l < LC; l++) {
        float es[H];
#pragma unroll
        for (int h = 0; h < H; h++) es[h] = Es[(h*NE + s)*(LC+1) + l];
#pragma unroll
        for (int tt = 0; tt < 7; tt++) {
            int t = t0 + tt;
            float acc = 0.0f;
#pragma unroll
            for (int h = 0; h < H; h++) acc += es[h] * Es[(h*NE + t)*(LC+1) + l];
            acc *= invH;
            size_t off = ((size_t)(b*NE2 + s*NE + t))*L + l0 + l;
            __nv_bfloat16 hv = __float2bfloat16(acc);
            g_htH[off] = hv;
            g_htL[off] = __float2bfloat16(acc - __bfloat162float(hv));
            rs[tt] += acc;
        }
    }
#pragma unroll
    for (int tt = 0; tt < 7; tt++)
        atomicAdd(&g_rowsum[b*NE2 + s*NE + t0 + tt], rs[tt]);
}

// ---------------------------------------------------------------------------
// K2b: split seq into bf16 hi/lo
// ---------------------------------------------------------------------------
__global__ void k_cvt_seq(const float* __restrict__ seq) {
    size_t i = (size_t)blockIdx.x * 256 + threadIdx.x;   // float4 index
    float4 v = ((const float4*)seq)[i];
    __nv_bfloat162 h0 = __floats2bfloat162_rn(v.x, v.y);
    __nv_bfloat162 h1 = __floats2bfloat162_rn(v.z, v.w);
    __nv_bfloat162 e0 = __floats2bfloat162_rn(v.x - __bfloat162float(h0.x),
                                              v.y - __bfloat162float(h0.y));
    __nv_bfloat162 e1 = __floats2bfloat162_rn(v.z - __bfloat162float(h1.x),
                                              v.w - __bfloat162float(h1.y));
    uint2 hi, lo;
    hi.x = *(uint32_t*)&h0; hi.y = *(uint32_t*)&h1;
    lo.x = *(uint32_t*)&e0; lo.y = *(uint32_t*)&e1;
    *(uint2*)&g_seqH[i*4] = hi;
    *(uint2*)&g_seqL[i*4] = lo;
}

// ---------------------------------------------------------------------------
// K3: mma.sync bf16 3-split GEMM, double-buffered cp.async pipeline.
// ---------------------------------------------------------------------------
#define BM 128
#define BN 128
#define BK 32
#define NKT (L/BK)

#define A_STRIDE 80     /* 64B data in 80B slot; 80/16=5 -> distinct 16B banks */
#define B_STRIDE 272    /* 256B data in 272B slot; 17 -> distinct banks */
#define OFF_AH 0
#define OFF_AL 10240
#define OFF_BH 20480
#define OFF_BL 29184
#define BUF_STRIDE 37888
#define SM_TOT (2*BUF_STRIDE)   /* 75776 */

__device__ __forceinline__ void cp16(uint32_t dst, const void* src) {
    asm volatile("cp.async.cg.shared.global [%0], [%1], 16;" :: "r"(dst), "l"(src) : "memory");
}
__device__ __forceinline__ void ldsm_x4(uint32_t* r, uint32_t addr) {
    asm volatile("ldmatrix.sync.aligned.m8n8.x4.shared.b16 {%0,%1,%2,%3}, [%4];"
                 : "=r"(r[0]), "=r"(r[1]), "=r"(r[2]), "=r"(r[3]) : "r"(addr));
}
__device__ __forceinline__ void ldsm_x4_t(uint32_t* r, uint32_t addr) {
    asm volatile("ldmatrix.sync.aligned.m8n8.x4.trans.shared.b16 {%0,%1,%2,%3}, [%4];"
                 : "=r"(r[0]), "=r"(r[1]), "=r"(r[2]), "=r"(r[3]) : "r"(addr));
}
__device__ __forceinline__ void mma_bf16(float* c, const uint32_t* a, const uint32_t* b) {
    asm volatile(
        "mma.sync.aligned.m16n8k16.row.col.f32.bf16.bf16.f32 "
        "{%0,%1,%2,%3}, {%4,%5,%6,%7}, {%8,%9}, {%0,%1,%2,%3};"
        : "+f"(c[0]), "+f"(c[1]), "+f"(c[2]), "+f"(c[3])
        : "r"(a[0]), "r"(a[1]), "r"(a[2]), "r"(a[3]), "r"(b[0]), "r"(b[1]));
}

__global__ __launch_bounds__(256, 2) void k_gemm(float* __restrict__ outp) {
    extern __shared__ __align__(16) char smem[];
    uint32_t sb = smem_u32(smem);

    int tid  = threadIdx.x;
    int wid  = tid >> 5;
    int lane = tid & 31;

    int b    = blockIdx.z;
    int row0 = blockIdx.x * BM;
    int col0 = blockIdx.y * BN;

    int wm = (wid & 3) * 32;
    int wn = (wid >> 2) * 64;

    float acc[2][8][4];
#pragma unroll
    for (int i = 0; i < 2; i++)
#pragma unroll
        for (int j = 0; j < 8; j++)
#pragma unroll
            for (int q = 0; q < 4; q++) acc[i][j][q] = 0.0f;

    // per-thread cp.async slot decomposition (constant across tiles)
    // A: 1024 ops = 2 arrays x 128 rows x 4 chunks of 16B (64B/row = BK bf16)
    int aArr[4], aR[4], aC[4];
    const __nv_bfloat16* aSrcBase[4];
#pragma unroll
    for (int i = 0; i < 4; i++) {
        int slot = tid + 256*i;
        aArr[i] = slot >> 9;           // 0..1
        int rem = slot & 511;
        aR[i] = rem >> 2;              // 0..127
        aC[i] = rem & 3;               // 0..3 (x16B = 64B)
        int grow = row0 + aR[i];
        if (grow >= NE2) grow = 0;
        const __nv_bfloat16* s = aArr[i] ? g_htL : g_htH;
        aSrcBase[i] = s + ((size_t)b*NE2 + grow)*L + aC[i]*8;
    }
    // B: 1024 ops = 2 arrays x 32 rows x 16 chunks of 16B (256B/row = 128 bf16)
    int bArr[4], bL[4], bC[4];
    const __nv_bfloat16* bSrcBase[4];
#pragma unroll
    for (int i = 0; i < 4; i++) {
        int slot = tid + 256*i;
        bArr[i] = slot >> 9;
        int rem = slot & 511;
        bL[i] = rem >> 4;
        bC[i] = rem & 15;
        const __nv_bfloat16* s = bArr[i] ? g_seqL : g_seqH;
        bSrcBase[i] = s + ((size_t)b*L + bL[i])*D + col0 + bC[i]*8;
    }

#define LOAD_TILE(kt, bufIdx) do { \
    uint32_t base_ = sb + (bufIdx)*BUF_STRIDE; \
    int l0_ = (kt)*BK; \
    _Pragma("unroll") \
    for (int i_ = 0; i_ < 4; i_++) \
        cp16(base_ + aArr[i_]*10240 + aR[i_]*A_STRIDE + aC[i_]*16, aSrcBase[i_] + l0_); \
    _Pragma("unroll") \
    for (int i_ = 0; i_ < 4; i_++) \
        cp16(base_ + OFF_BH + bArr[i_]*8704 + bL[i_]*B_STRIDE + bC[i_]*16, \
             bSrcBase[i_] + (size_t)l0_*D); \
    asm volatile("cp.async.commit_group;" ::: "memory"); \
} while (0)

    int lr  = lane & 15;
    int lc8 = (lane >> 4) << 3;
    uint32_t aOffH = (wm + lr) * A_STRIDE + lc8 * 2;
    uint32_t bOffH = lr * B_STRIDE + (wn + lc8) * 2;

    LOAD_TILE(0, 0);

    for (int kt = 0; kt < NKT; kt++) {
        if (kt + 1 < NKT) {
            LOAD_TILE(kt + 1, (kt + 1) & 1);
            asm volatile("cp.async.wait_group 1;" ::: "memory");
        } else {
            asm volatile("cp.async.wait_group 0;" ::: "memory");
        }
        __syncthreads();

        uint32_t base = sb + (kt & 1) * BUF_STRIDE;
        uint32_t aAddrH = base + OFF_AH + aOffH;
        uint32_t aAddrL = base + OFF_AL + aOffH;
        uint32_t bAddrH = base + OFF_BH + bOffH;
        uint32_t bAddrL = base + OFF_BL + bOffH;

#pragma unroll
        for (int ks = 0; ks < 2; ks++) {
            int kb = ks * 32;
            uint32_t ah[2][4], al[2][4];
            ldsm_x4(ah[0], aAddrH + kb);
            ldsm_x4(ah[1], aAddrH + 16*A_STRIDE + kb);
            ldsm_x4(al[0], aAddrL + kb);
            ldsm_x4(al[1], aAddrL + 16*A_STRIDE + kb);

            uint32_t bh[4][4], bl[4][4];
#pragma unroll
            for (int nb = 0; nb < 4; nb++) {
                ldsm_x4_t(bh[nb], bAddrH + ks*16*B_STRIDE + nb*32);
                ldsm_x4_t(bl[nb], bAddrL + ks*16*B_STRIDE + nb*32);
            }
#pragma unroll
            for (int mi = 0; mi < 2; mi++) {
#pragma unroll
                for (int nj = 0; nj < 8; nj++) {
                    const uint32_t* bfh = &bh[nj>>1][(nj&1)*2];
                    const uint32_t* bfl = &bl[nj>>1][(nj&1)*2];
                    mma_bf16(acc[mi][nj], ah[mi], bfh);
                    mma_bf16(acc[mi][nj], ah[mi], bfl);
                    mma_bf16(acc[mi][nj], al[mi], bfh);
                }
            }
        }
        __syncthreads();
    }

    // ---- Epilogue ----
    int g = lane >> 2;
    int t = lane & 3;
#pragma unroll
    for (int mi = 0; mi < 2; mi++) {
#pragma unroll
        for (int half = 0; half < 2; half++) {
            int grow = row0 + wm + mi*16 + g + half*8;
            if (grow >= NE2) continue;
            float scale = 1.0f / (g_rowsum[b*NE2 + grow] + 1e-5f);
            float* op = outp + ((size_t)(b*NE2 + grow))*D + col0 + wn;
#pragma unroll
            for (int nj = 0; nj < 8; nj++) {
                float2 v;
                v.x = acc[mi][nj][half*2+0] * scale;
                v.y = acc[mi][nj][half*2+1] * scale;
                *(float2*)&op[nj*8 + t*2] = v;
            }
        }
    }
}

// ---------------------------------------------------------------------------
extern "C" void kernel_launch(void* const* d_in, const int* in_sizes, int n_in,
                              void* d_out, int out_size) {
    const float* seq   = (const float*)d_in[0];
    const float* att   = (const float*)d_in[1];
    const int*   midx  = (const int*)d_in[2];
    const int*   mmask = (const int*)d_in[3];
    float* outp = (float*)d_out;

    void* rsPtr = nullptr;
    cudaGetSymbolAddress(&rsPtr, g_rowsum);
    cudaMemsetAsync(rsPtr, 0, B*NE2*sizeof(float));

    k_ent_att<<<B*H*NE, 256>>>(att, midx, mmask);
    k_cvt_seq<<<(B*L*D/4 + 255)/256, 256>>>(seq);
    k_ht<<<B*(L/LC), 256>>>();

    cudaFuncSetAttribute(k_gemm, cudaFuncAttributeMaxDynamicSharedMemorySize, SM_TOT);
    dim3 grid((NE2 + BM - 1)/BM, D/BN, B);
    k_gemm<<<grid, 256, SM_TOT>>>(outp);
}